// round 15
// baseline (speedup 1.0000x reference)
#include <cuda_runtime.h>
#include <cuda_fp16.h>
#include <cstdint>

// ---------------- problem constants ----------------
#define T_TOK 50176     // 64*28*28 tokens
#define D_IN  512
#define D_HID 2048
#define K2    2112      // D_HID + 24 moe cols + 40 zero pad (multiple of 64)
#define N_EXP 3
#define R_LORA 8

#define NROW  392       // token row-blocks of 128
// jobs: 392 lora + 3136 gemm1 pairs + 784 gemm2 pairs
#define NJOBS 4312

// ---------------- device scratch ----------------
__device__ __half g_xh[(size_t)T_TOK * D_IN];        // x in fp16
__device__ __half g_w1t[(size_t)D_HID * D_IN];       // W1^T [2048,512]
__device__ __half g_w2e[(size_t)D_IN * K2];          // [512,2112] = W2^T ++ w_up^T ++ 0
__device__ __half g_wdt[(size_t)32 * D_IN];          // w_down^T padded [32,512]
__device__ __half g_h[(size_t)T_TOK * K2];           // hidden ++ a24 ++ 0-pad
__device__ int    g_ticket;
__device__ int    g_rowdone[NROW];

__device__ __forceinline__ float gelu_exact(float v) {
    return 0.5f * v * (1.0f + erff(v * 0.70710678118654752f));
}
__device__ __forceinline__ uint32_t smem_to_u32(const void* p) {
    uint32_t a;
    asm("{ .reg .u64 t; cvta.to.shared.u64 t, %1; cvt.u32.u64 %0, t; }" : "=r"(a) : "l"(p));
    return a;
}

// ---------------- base-ISA async copy / ldmatrix / mma helpers ----------
#define CP_ASYNC16(dst_smem, src_gmem) \
    asm volatile("cp.async.cg.shared.global [%0], [%1], 16;" \
        :: "r"(dst_smem), "l"(src_gmem) : "memory")
#define CP_COMMIT() asm volatile("cp.async.commit_group;" ::: "memory")
#define CP_WAIT1()  asm volatile("cp.async.wait_group 1;" ::: "memory")
#define CP_WAIT0()  asm volatile("cp.async.wait_group 0;" ::: "memory")

#define LDMATRIX_X4(r0, r1, r2, r3, addr) \
    asm volatile("ldmatrix.sync.aligned.m8n8.x4.shared.b16 {%0,%1,%2,%3}, [%4];" \
        : "=r"(r0), "=r"(r1), "=r"(r2), "=r"(r3) : "r"(addr))

#define MMA_FP16(c, a, b0_, b1_) \
    asm volatile("mma.sync.aligned.m16n8k16.row.col.f32.f16.f16.f32 " \
        "{%0,%1,%2,%3}, {%4,%5,%6,%7}, {%8,%9}, {%0,%1,%2,%3};" \
        : "+f"((c)[0]), "+f"((c)[1]), "+f"((c)[2]), "+f"((c)[3]) \
        : "r"((a)[0]), "r"((a)[1]), "r"((a)[2]), "r"((a)[3]), "r"(b0_), "r"(b1_))

// =====================================================================
// Fused prep: reset + x cvt + all weight prep in ONE launch.
// =====================================================================
#define CVT_BLKS   25088   // 50176*512/4/256
#define PREP_BLKS  (CVT_BLKS + 1024 + 1024 + 192 + 1)

__global__ __launch_bounds__(256) void prep_all_kernel(
    const float* __restrict__ x,
    const float* __restrict__ W1, const float* __restrict__ W2,
    const float* __restrict__ w_up, const float* __restrict__ w_down)
{
    __shared__ float tile[32][33];
    int b = blockIdx.x;
    if (b < CVT_BLKS) {
        int i = b * 256 + threadIdx.x;
        float4 v = ((const float4*)x)[i];
        ((__half2*)g_xh)[2*i]   = __floats2half2_rn(v.x, v.y);
        ((__half2*)g_xh)[2*i+1] = __floats2half2_rn(v.z, v.w);
        return;
    }
    b -= CVT_BLKS;
    int tx = threadIdx.x & 31, ty = threadIdx.x >> 5;
    if (b < 1024) {
        int c0 = (b & 63) * 32, r0 = (b >> 6) * 32;   // cols of W1 (2048), rows (512)
        #pragma unroll
        for (int i = 0; i < 4; i++)
            tile[ty + 8*i][tx] = W1[(size_t)(r0 + ty + 8*i) * D_HID + c0 + tx];
        __syncthreads();
        #pragma unroll
        for (int i = 0; i < 4; i++)
            g_w1t[(size_t)(c0 + ty + 8*i) * D_IN + r0 + tx] = __float2half_rn(tile[tx][ty + 8*i]);
    } else if (b < 2048) {
        int b2 = b - 1024;
        int c0 = (b2 & 15) * 32, r0 = (b2 >> 4) * 32; // cols of W2 (512), rows (2048)
        #pragma unroll
        for (int i = 0; i < 4; i++)
            tile[ty + 8*i][tx] = W2[(size_t)(r0 + ty + 8*i) * D_IN + c0 + tx];
        __syncthreads();
        #pragma unroll
        for (int i = 0; i < 4; i++)
            g_w2e[(size_t)(c0 + ty + 8*i) * K2 + r0 + tx] = __float2half_rn(tile[tx][ty + 8*i]);
    } else if (b < 2240) {
        int b3 = b - 2048;
        if (b3 < 128) {
            int i = b3 * 256 + threadIdx.x;          // over 512*64
            int n = i >> 6, c = i & 63;
            float v = 0.0f;
            if (c < N_EXP * R_LORA) v = w_up[(size_t)c * D_IN + n];
            g_w2e[(size_t)n * K2 + D_HID + c] = __float2half_rn(v);
        } else {
            int i = (b3 - 128) * 256 + threadIdx.x;  // over 32*512
            int n = i >> 9, d = i & 511;
            float v = 0.0f;
            if (n < N_EXP * R_LORA) {
                int e = n >> 3, r = n & 7;
                v = w_down[(size_t)e * (D_IN * R_LORA) + (size_t)d * R_LORA + r];
            }
            g_wdt[(size_t)n * D_IN + d] = __float2half_rn(v);
        }
    } else {
        int i = threadIdx.x;
        if (i == 0) g_ticket = 0;
        for (int j = i; j < NROW; j += 256) g_rowdone[j] = 0;
    }
}

// =====================================================================
// Mega-kernel pieces (128-thread CTAs, 3 CTA/SM)
// =====================================================================
#define MAT_BYTES 18432     // 128 * 72 * 2
#define STAGE_BYTES 36864   // A + B
#define GSMEM_BYTES (2 * STAGE_BYTES + 512)

#define LMAT_A 10240        // lora k32 / pitch-80 layout
#define LSTAGE 12800

// --- LoRA job: down = x @ wdt^T [128 tok x 32], gated-gelu epilogue ---
__device__ void do_lora(int m, const float* __restrict__ probs,
                        const int* __restrict__ idx, char* sm, int tid)
{
    uint32_t sb = smem_to_u32(sm);
    int lane = tid & 31, w = tid >> 5;
    int mBase = m * 128;
    const int NS = D_IN / 32;   // 16

    float acc[2][4][4];
    #pragma unroll
    for (int i = 0; i < 2; i++)
        #pragma unroll
        for (int j = 0; j < 4; j++)
            #pragma unroll
            for (int q = 0; q < 4; q++) acc[i][j][q] = 0.0f;

    auto issue = [&](int s) {
        uint32_t sbuf = sb + (uint32_t)(s % 3) * LSTAGE;
        int kt = s * 32;
        #pragma unroll
        for (int c = 0; c < 4; ++c) {
            int q = tid + 128 * c;
            int row = q >> 2, ch = q & 3;
            CP_ASYNC16(sbuf + (uint32_t)row * 80 + (uint32_t)ch * 16,
                       g_xh + (size_t)(mBase + row) * D_IN + kt + ch * 8);
        }
        {
            int row = tid >> 2, ch = tid & 3;
            CP_ASYNC16(sbuf + LMAT_A + (uint32_t)row * 80 + (uint32_t)ch * 16,
                       g_wdt + (size_t)row * D_IN + kt + ch * 8);
        }
    };

    issue(0); CP_COMMIT();
    issue(1); CP_COMMIT();

    uint32_t a_off = (uint32_t)(w * 32 + (lane & 15)) * 80 + (uint32_t)((lane >> 4) * 8) * 2;
    uint32_t b_off = LMAT_A + (uint32_t)((lane & 7) + ((lane >> 4) << 3)) * 80
                   + (uint32_t)(((lane >> 3) & 1) * 8) * 2;

    #pragma unroll 1
    for (int s = 0; s < NS; ++s) {
        CP_WAIT1();
        __syncthreads();
        if (s + 2 < NS) issue(s + 2);
        CP_COMMIT();

        uint32_t buf = sb + (uint32_t)(s % 3) * LSTAGE;
        #pragma unroll
        for (int ks = 0; ks < 2; ++ks) {
            uint32_t kb = (uint32_t)ks * 32;
            uint32_t ah[2][4], bh[4][2];
            #pragma unroll
            for (int i = 0; i < 2; ++i)
                LDMATRIX_X4(ah[i][0], ah[i][1], ah[i][2], ah[i][3],
                            buf + a_off + (uint32_t)(i * 16) * 80 + kb);
            #pragma unroll
            for (int jj = 0; jj < 2; ++jj)
                LDMATRIX_X4(bh[2*jj][0], bh[2*jj][1], bh[2*jj+1][0], bh[2*jj+1][1],
                            buf + b_off + (uint32_t)(jj * 16) * 80 + kb);
            #pragma unroll
            for (int i = 0; i < 2; ++i)
                #pragma unroll
                for (int j = 0; j < 4; ++j)
                    MMA_FP16(acc[i][j], ah[i], bh[j][0], bh[j][1]);
        }
    }
    __syncthreads();   // reads done before smem reuse by next job

    int g = lane >> 2, tq = lane & 3;
    #pragma unroll
    for (int i = 0; i < 2; ++i) {
        int t0 = mBase + w * 32 + i * 16 + g;
        int t1 = t0 + 8;
        int e00 = idx[2*t0], e01 = idx[2*t0+1];
        int e10 = idx[2*t1], e11 = idx[2*t1+1];
        float p00 = probs[2*t0], p01 = probs[2*t0+1];
        float p10 = probs[2*t1], p11 = probs[2*t1+1];
        #pragma unroll
        for (int j = 0; j < 3; ++j) {          // j == expert id
            float w0 = (e00 == j) ? p00 : ((e01 == j) ? p01 : 0.0f);
            float w1 = (e10 == j) ? p10 : ((e11 == j) ? p11 : 0.0f);
            float v0 = w0 * gelu_exact(acc[i][j][0]);
            float v1 = w0 * gelu_exact(acc[i][j][1]);
            float v2 = w1 * gelu_exact(acc[i][j][2]);
            float v3 = w1 * gelu_exact(acc[i][j][3]);
            int c = j * 8 + tq * 2;
            *(__half2*)(g_h + (size_t)t0 * K2 + D_HID + c) = __floats2half2_rn(v0, v1);
            *(__half2*)(g_h + (size_t)t1 * K2 + D_HID + c) = __floats2half2_rn(v2, v3);
        }
    }
}

// --- GEMM pair job: two adjacent 128x128 n-tiles of the same m row.
//     k64 stages, 2-buffer cp.async, A-fragment splice.  Tile1's stage-0
//     is issued during tile0's last stage -> prologue hides under
//     tile0's epilogue.  Buffer parity for tile1 = NS & 1. ---
template<int KTOT, int LD, bool IS_GEMM1>
__device__ void do_gemm_pair(int mBase, int nBase0,
                             const __half* __restrict__ A, const __half* __restrict__ B,
                             const float* __restrict__ bias,
                             __half* __restrict__ OutH, float* __restrict__ OutF,
                             char* sm, int tid)
{
    uint32_t sb = smem_to_u32(sm);
    float* bias_s = (float*)(sm + 2 * STAGE_BYTES);

    int lane = tid & 31, wid = tid >> 5;
    int wm = wid >> 1, wn = wid & 1;          // warp grid 2 x 2

    int r0 = tid >> 3, ch = tid & 7;
    size_t gArow = (size_t)(mBase + r0) * LD + ch * 8;
    uint32_t soA = (uint32_t)r0 * 144 + (uint32_t)ch * 16;

    const int NS = KTOT / 64;
    const int BASE1 = NS & 1;

    auto issue = [&](int s, int nBase, int base) {
        uint32_t sbuf = sb + (uint32_t)((s + base) & 1) * STAGE_BYTES;
        int kt = s * 64;
        size_t gBrow = (size_t)(nBase + r0) * LD + ch * 8;
        #pragma unroll
        for (int c = 0; c < 8; ++c)
            CP_ASYNC16(sbuf + soA + (uint32_t)(16 * c) * 144,
                       A + gArow + (size_t)(16 * c) * LD + kt);
        #pragma unroll
        for (int c = 0; c < 8; ++c)
            CP_ASYNC16(sbuf + MAT_BYTES + soA + (uint32_t)(16 * c) * 144,
                       B + gBrow + (size_t)(16 * c) * LD + kt);
    };

    uint32_t a_off = (uint32_t)(wm * 64 + (lane & 15)) * 144 + (uint32_t)((lane >> 4) * 8) * 2;
    uint32_t b_off = (uint32_t)(wn * 64 + (lane & 7) + ((lane >> 4) << 3)) * 144
                   + (uint32_t)(((lane >> 3) & 1) * 8) * 2;

    bias_s[tid] = bias[nBase0 + tid];
    issue(0, nBase0, 0); CP_COMMIT();

    #pragma unroll 1
    for (int tile = 0; tile < 2; ++tile) {
        int nBase = nBase0 + tile * 128;
        int base = tile ? BASE1 : 0;

        float acc[4][8][4];
        #pragma unroll
        for (int i = 0; i < 4; i++)
            #pragma unroll
            for (int j = 0; j < 8; j++)
                #pragma unroll
                for (int q = 0; q < 4; q++) acc[i][j][q] = 0.0f;

        #pragma unroll 1
        for (int s = 0; s < NS; ++s) {
            CP_WAIT0();
            __syncthreads();

            uint32_t buf = sb + (uint32_t)((s + base) & 1) * STAGE_BYTES;

            // splice: ks=0 A fragments before issuing next loads
            uint32_t ah[4][4];
            #pragma unroll
            for (int i = 0; i < 4; ++i)
                LDMATRIX_X4(ah[i][0], ah[i][1], ah[i][2], ah[i][3],
                            buf + a_off + (uint32_t)(i * 16) * 144);

            if (s + 1 < NS)        issue(s + 1, nBase, base);
            else if (tile == 0)    issue(0, nBase0 + 128, BASE1);  // tile1 stage0
            CP_COMMIT();

            #pragma unroll
            for (int ks = 0; ks < 4; ++ks) {
                uint32_t kb = (uint32_t)ks * 32;
                if (ks > 0) {
                    #pragma unroll
                    for (int i = 0; i < 4; ++i)
                        LDMATRIX_X4(ah[i][0], ah[i][1], ah[i][2], ah[i][3],
                                    buf + a_off + (uint32_t)(i * 16) * 144 + kb);
                }
                #pragma unroll
                for (int h = 0; h < 2; ++h) {
                    uint32_t bh[4][2];
                    #pragma unroll
                    for (int jj = 0; jj < 2; ++jj)
                        LDMATRIX_X4(bh[2*jj][0], bh[2*jj][1], bh[2*jj+1][0], bh[2*jj+1][1],
                                    buf + MAT_BYTES + b_off
                                    + (uint32_t)(h * 32 + jj * 16) * 144 + kb);
                    #pragma unroll
                    for (int i = 0; i < 4; ++i)
                        #pragma unroll
                        for (int j = 0; j < 4; ++j)
                            MMA_FP16(acc[i][h * 4 + j], ah[i], bh[j][0], bh[j][1]);
                }
            }
        }
        __syncthreads();   // reads done before buffer reuse

        // epilogue for this tile (tile1's stage-0 load is in flight under it)
        int g = lane >> 2, tq = lane & 3;
        #pragma unroll
        for (int i = 0; i < 4; ++i) {
            int row0 = mBase + wm * 64 + i * 16 + g;
            int row1 = row0 + 8;
            #pragma unroll
            for (int j = 0; j < 8; ++j) {
                int nloc = wn * 64 + j * 8 + tq * 2;
                float b0 = bias_s[nloc], b1 = bias_s[nloc + 1];
                float v0 = acc[i][j][0] + b0, v1 = acc[i][j][1] + b1;
                float v2 = acc[i][j][2] + b0, v3 = acc[i][j][3] + b1;
                if (IS_GEMM1) {
                    v0 = gelu_exact(v0); v1 = gelu_exact(v1);
                    v2 = gelu_exact(v2); v3 = gelu_exact(v3);
                    size_t o0 = (size_t)row0 * K2 + nBase + nloc;
                    size_t o1 = (size_t)row1 * K2 + nBase + nloc;
                    *(__half2*)(OutH + o0) = __floats2half2_rn(v0, v1);
                    *(__half2*)(OutH + o1) = __floats2half2_rn(v2, v3);
                } else {
                    size_t o0 = (size_t)row0 * D_IN + nBase + nloc;
                    size_t o1 = (size_t)row1 * D_IN + nBase + nloc;
                    *(float2*)(OutF + o0) = make_float2(v0, v1);
                    *(float2*)(OutF + o1) = make_float2(v2, v3);
                }
            }
        }

        if (tile == 0) {
            __syncthreads();                      // bias_s reads done
            bias_s[tid] = bias[nBase0 + 128 + tid];
        }
    }
}

// --- persistent scheduler (paired-tile job map) ---
// tickets: [0,392) lora m | [392,776) g1 pairs rows 0..47 (m=j>>3,p=j&7) |
//          [776,4216): 344 blocks of 10: 8 g1 (row 48+b, pair r) + 2 g2
//          (row b, pair r-8) | [4216,4312): trailing g2 rows 344..391.
__global__ __launch_bounds__(128, 3) void mega_kernel(
    const float* __restrict__ b1, const float* __restrict__ b2,
    const float* __restrict__ probs, const int* __restrict__ idx,
    float* __restrict__ out)
{
    extern __shared__ char sm[];
    __shared__ int s_job;
    int tid = threadIdx.x;

    for (;;) {
        __syncthreads();
        if (tid == 0) s_job = atomicAdd(&g_ticket, 1);
        __syncthreads();
        int job = s_job;
        if (job >= NJOBS) return;

        int type, m, p = 0;
        if (job < 392) { type = 0; m = job; }
        else {
            int j = job - 392;
            if (j < 384) { type = 1; m = j >> 3; p = j & 7; }
            else if (j < 3824) {
                int t = j - 384, b = t / 10, r = t % 10;
                if (r < 8) { type = 1; m = 48 + b; p = r; }
                else       { type = 2; m = b;      p = r - 8; }
            } else {
                int t = j - 3824; type = 2; m = 344 + (t >> 1); p = t & 1;
            }
        }

        if (type == 0) {
            do_lora(m, probs, idx, sm, tid);
            __threadfence();
            __syncthreads();
            if (tid == 0) atomicAdd(&g_rowdone[m], 1);
        } else if (type == 1) {
            do_gemm_pair<D_IN, D_IN, true>(m * 128, p * 256, g_xh, g_w1t, b1,
                                           g_h, nullptr, sm, tid);
            __threadfence();
            __syncthreads();
            if (tid == 0) atomicAdd(&g_rowdone[m], 1);
        } else {
            if (tid == 0) {
                while (atomicAdd(&g_rowdone[m], 0) < 9) __nanosleep(128);
            }
            __syncthreads();
            __threadfence();
            do_gemm_pair<K2, K2, false>(m * 128, p * 256, g_h, g_w2e, b2,
                                        nullptr, out, sm, tid);
        }
    }
}

// =====================================================================
// launch
// =====================================================================
extern "C" void kernel_launch(void* const* d_in, const int* in_sizes, int n_in,
                              void* d_out, int out_size) {
    const float* x          = (const float*)d_in[0];
    const float* W1         = (const float*)d_in[1];
    const float* b1         = (const float*)d_in[2];
    const float* W2         = (const float*)d_in[3];
    const float* b2         = (const float*)d_in[4];
    const float* w_down     = (const float*)d_in[5];
    const float* w_up       = (const float*)d_in[6];
    const float* topk_probs = (const float*)d_in[8];
    const int*   topk_idx   = (const int*)d_in[9];
    float* out = (float*)d_out;
    (void)in_sizes; (void)n_in; (void)out_size;

    cudaFuncSetAttribute(mega_kernel,
                         cudaFuncAttributeMaxDynamicSharedMemorySize, GSMEM_BYTES);

    prep_all_kernel<<<PREP_BLKS, 256>>>(x, W1, W2, w_up, w_down);
    mega_kernel<<<444, 128, GSMEM_BYTES>>>(b1, b2, topk_probs, topk_idx, out);
}

// round 16
// speedup vs baseline: 1.1088x; 1.1088x over previous
#include <cuda_runtime.h>
#include <cuda_fp16.h>
#include <cstdint>

// ---------------- problem constants ----------------
#define T_TOK 50176     // 64*28*28 tokens
#define D_IN  512
#define D_HID 2048
#define K2    2112      // D_HID + 24 moe cols + 40 zero pad (multiple of 64)
#define N_EXP 3
#define R_LORA 8

#define NROW  392       // token row-blocks of 128
#define NJOBS 8232      // 392 lora + 6272 gemm1 + 1568 gemm2 (interleaved map)

// ---------------- device scratch ----------------
__device__ __half g_xh[(size_t)T_TOK * D_IN];        // x in fp16
__device__ __half g_w1t[(size_t)D_HID * D_IN];       // W1^T [2048,512]
__device__ __half g_w2e[(size_t)D_IN * K2];          // [512,2112] = W2^T ++ w_up^T ++ 0
__device__ __half g_wdt[(size_t)32 * D_IN];          // w_down^T padded [32,512]
__device__ __half g_h[(size_t)T_TOK * K2];           // hidden ++ a24 ++ 0-pad
__device__ int    g_ticket;
__device__ int    g_rowdone[NROW];

__device__ __forceinline__ float gelu_exact(float v) {
    return 0.5f * v * (1.0f + erff(v * 0.70710678118654752f));
}
__device__ __forceinline__ uint32_t smem_to_u32(const void* p) {
    uint32_t a;
    asm("{ .reg .u64 t; cvta.to.shared.u64 t, %1; cvt.u32.u64 %0, t; }" : "=r"(a) : "l"(p));
    return a;
}

// ---------------- base-ISA async copy / ldmatrix / mma helpers ----------
#define CP_ASYNC16(dst_smem, src_gmem) \
    asm volatile("cp.async.cg.shared.global [%0], [%1], 16;" \
        :: "r"(dst_smem), "l"(src_gmem) : "memory")
#define CP_COMMIT() asm volatile("cp.async.commit_group;" ::: "memory")
#define CP_WAIT1()  asm volatile("cp.async.wait_group 1;" ::: "memory")
#define CP_WAIT0()  asm volatile("cp.async.wait_group 0;" ::: "memory")

#define LDMATRIX_X4(r0, r1, r2, r3, addr) \
    asm volatile("ldmatrix.sync.aligned.m8n8.x4.shared.b16 {%0,%1,%2,%3}, [%4];" \
        : "=r"(r0), "=r"(r1), "=r"(r2), "=r"(r3) : "r"(addr))

#define MMA_FP16(c, a, b0_, b1_) \
    asm volatile("mma.sync.aligned.m16n8k16.row.col.f32.f16.f16.f32 " \
        "{%0,%1,%2,%3}, {%4,%5,%6,%7}, {%8,%9}, {%0,%1,%2,%3};" \
        : "+f"((c)[0]), "+f"((c)[1]), "+f"((c)[2]), "+f"((c)[3]) \
        : "r"((a)[0]), "r"((a)[1]), "r"((a)[2]), "r"((a)[3]), "r"(b0_), "r"(b1_))

// =====================================================================
// Fused prep: reset + x cvt + all weight prep in ONE launch.
// =====================================================================
#define CVT_BLKS   25088   // 50176*512/4/256
#define PREP_BLKS  (CVT_BLKS + 1024 + 1024 + 192 + 1)

__global__ __launch_bounds__(256) void prep_all_kernel(
    const float* __restrict__ x,
    const float* __restrict__ W1, const float* __restrict__ W2,
    const float* __restrict__ w_up, const float* __restrict__ w_down)
{
    __shared__ float tile[32][33];
    int b = blockIdx.x;
    if (b < CVT_BLKS) {
        int i = b * 256 + threadIdx.x;
        float4 v = ((const float4*)x)[i];
        ((__half2*)g_xh)[2*i]   = __floats2half2_rn(v.x, v.y);
        ((__half2*)g_xh)[2*i+1] = __floats2half2_rn(v.z, v.w);
        return;
    }
    b -= CVT_BLKS;
    int tx = threadIdx.x & 31, ty = threadIdx.x >> 5;
    if (b < 1024) {
        int c0 = (b & 63) * 32, r0 = (b >> 6) * 32;   // cols of W1 (2048), rows (512)
        #pragma unroll
        for (int i = 0; i < 4; i++)
            tile[ty + 8*i][tx] = W1[(size_t)(r0 + ty + 8*i) * D_HID + c0 + tx];
        __syncthreads();
        #pragma unroll
        for (int i = 0; i < 4; i++)
            g_w1t[(size_t)(c0 + ty + 8*i) * D_IN + r0 + tx] = __float2half_rn(tile[tx][ty + 8*i]);
    } else if (b < 2048) {
        int b2 = b - 1024;
        int c0 = (b2 & 15) * 32, r0 = (b2 >> 4) * 32; // cols of W2 (512), rows (2048)
        #pragma unroll
        for (int i = 0; i < 4; i++)
            tile[ty + 8*i][tx] = W2[(size_t)(r0 + ty + 8*i) * D_IN + c0 + tx];
        __syncthreads();
        #pragma unroll
        for (int i = 0; i < 4; i++)
            g_w2e[(size_t)(c0 + ty + 8*i) * K2 + r0 + tx] = __float2half_rn(tile[tx][ty + 8*i]);
    } else if (b < 2240) {
        int b3 = b - 2048;
        if (b3 < 128) {
            int i = b3 * 256 + threadIdx.x;          // over 512*64
            int n = i >> 6, c = i & 63;
            float v = 0.0f;
            if (c < N_EXP * R_LORA) v = w_up[(size_t)c * D_IN + n];
            g_w2e[(size_t)n * K2 + D_HID + c] = __float2half_rn(v);
        } else {
            int i = (b3 - 128) * 256 + threadIdx.x;  // over 32*512
            int n = i >> 9, d = i & 511;
            float v = 0.0f;
            if (n < N_EXP * R_LORA) {
                int e = n >> 3, r = n & 7;
                v = w_down[(size_t)e * (D_IN * R_LORA) + (size_t)d * R_LORA + r];
            }
            g_wdt[(size_t)n * D_IN + d] = __float2half_rn(v);
        }
    } else {
        int i = threadIdx.x;
        if (i == 0) g_ticket = 0;
        for (int j = i; j < NROW; j += 256) g_rowdone[j] = 0;
    }
}

// =====================================================================
// Mega-kernel pieces (128-thread CTAs, 3 CTA/SM)
// GEMM stage = k64: per matrix 128 rows x 72 halfs (144 B pitch).
// =====================================================================
#define MAT_BYTES 18432     // 128 * 72 * 2
#define STAGE_BYTES 36864   // A + B
#define GSMEM_BYTES (2 * STAGE_BYTES + 512)

#define LMAT_A 10240        // lora keeps k32 / pitch-80 layout
#define LSTAGE 12800

// --- LoRA job: down = x @ wdt^T [128 tok x 32], gated-gelu epilogue ---
__device__ void do_lora(int m, const float* __restrict__ probs,
                        const int* __restrict__ idx, char* sm, int tid)
{
    uint32_t sb = smem_to_u32(sm);
    int lane = tid & 31, w = tid >> 5;
    int mBase = m * 128;
    const int NS = D_IN / 32;   // 16

    float acc[2][4][4];
    #pragma unroll
    for (int i = 0; i < 2; i++)
        #pragma unroll
        for (int j = 0; j < 4; j++)
            #pragma unroll
            for (int q = 0; q < 4; q++) acc[i][j][q] = 0.0f;

    auto issue = [&](int s) {
        uint32_t sbuf = sb + (uint32_t)(s % 3) * LSTAGE;
        int kt = s * 32;
        #pragma unroll
        for (int c = 0; c < 4; ++c) {
            int q = tid + 128 * c;
            int row = q >> 2, ch = q & 3;
            CP_ASYNC16(sbuf + (uint32_t)row * 80 + (uint32_t)ch * 16,
                       g_xh + (size_t)(mBase + row) * D_IN + kt + ch * 8);
        }
        {
            int row = tid >> 2, ch = tid & 3;
            CP_ASYNC16(sbuf + LMAT_A + (uint32_t)row * 80 + (uint32_t)ch * 16,
                       g_wdt + (size_t)row * D_IN + kt + ch * 8);
        }
    };

    issue(0); CP_COMMIT();
    issue(1); CP_COMMIT();

    uint32_t a_off = (uint32_t)(w * 32 + (lane & 15)) * 80 + (uint32_t)((lane >> 4) * 8) * 2;
    uint32_t b_off = LMAT_A + (uint32_t)((lane & 7) + ((lane >> 4) << 3)) * 80
                   + (uint32_t)(((lane >> 3) & 1) * 8) * 2;

    #pragma unroll 1
    for (int s = 0; s < NS; ++s) {
        CP_WAIT1();
        __syncthreads();
        if (s + 2 < NS) issue(s + 2);
        CP_COMMIT();

        uint32_t buf = sb + (uint32_t)(s % 3) * LSTAGE;
        #pragma unroll
        for (int ks = 0; ks < 2; ++ks) {
            uint32_t kb = (uint32_t)ks * 32;
            uint32_t ah[2][4], bh[4][2];
            #pragma unroll
            for (int i = 0; i < 2; ++i)
                LDMATRIX_X4(ah[i][0], ah[i][1], ah[i][2], ah[i][3],
                            buf + a_off + (uint32_t)(i * 16) * 80 + kb);
            #pragma unroll
            for (int jj = 0; jj < 2; ++jj)
                LDMATRIX_X4(bh[2*jj][0], bh[2*jj][1], bh[2*jj+1][0], bh[2*jj+1][1],
                            buf + b_off + (uint32_t)(jj * 16) * 80 + kb);
            #pragma unroll
            for (int i = 0; i < 2; ++i)
                #pragma unroll
                for (int j = 0; j < 4; ++j)
                    MMA_FP16(acc[i][j], ah[i], bh[j][0], bh[j][1]);
        }
    }
    __syncthreads();   // reads done before smem reuse by next job

    int g = lane >> 2, tq = lane & 3;
    #pragma unroll
    for (int i = 0; i < 2; ++i) {
        int t0 = mBase + w * 32 + i * 16 + g;
        int t1 = t0 + 8;
        int e00 = idx[2*t0], e01 = idx[2*t0+1];
        int e10 = idx[2*t1], e11 = idx[2*t1+1];
        float p00 = probs[2*t0], p01 = probs[2*t0+1];
        float p10 = probs[2*t1], p11 = probs[2*t1+1];
        #pragma unroll
        for (int j = 0; j < 3; ++j) {          // j == expert id
            float w0 = (e00 == j) ? p00 : ((e01 == j) ? p01 : 0.0f);
            float w1 = (e10 == j) ? p10 : ((e11 == j) ? p11 : 0.0f);
            float v0 = w0 * gelu_exact(acc[i][j][0]);
            float v1 = w0 * gelu_exact(acc[i][j][1]);
            float v2 = w1 * gelu_exact(acc[i][j][2]);
            float v3 = w1 * gelu_exact(acc[i][j][3]);
            int c = j * 8 + tq * 2;
            *(__half2*)(g_h + (size_t)t0 * K2 + D_HID + c) = __floats2half2_rn(v0, v1);
            *(__half2*)(g_h + (size_t)t1 * K2 + D_HID + c) = __floats2half2_rn(v2, v3);
        }
    }
}

// --- GEMM job: CTA 128x128, 4 warps (64x64), k64 stages, 2-buffer
//     cp.async pipeline with A-fragment splice. (round-13 proven body) ---
template<int KTOT, int LD, bool IS_GEMM1>
__device__ void do_gemm(int mBase, int nBase,
                        const __half* __restrict__ A, const __half* __restrict__ B,
                        const float* __restrict__ bias,
                        __half* __restrict__ OutH, float* __restrict__ OutF,
                        char* sm, int tid)
{
    uint32_t sb = smem_to_u32(sm);
    float* bias_s = (float*)(sm + 2 * STAGE_BYTES);

    int lane = tid & 31, wid = tid >> 5;
    int wm = wid >> 1, wn = wid & 1;          // warp grid 2 x 2

    bias_s[tid] = bias[nBase + tid];

    int r0 = tid >> 3, ch = tid & 7;
    size_t gA = (size_t)(mBase + r0) * LD + ch * 8;
    size_t gB = (size_t)(nBase + r0) * LD + ch * 8;
    uint32_t soA = (uint32_t)r0 * 144 + (uint32_t)ch * 16;

    const int NS = KTOT / 64;

    float acc[4][8][4];
    #pragma unroll
    for (int i = 0; i < 4; i++)
        #pragma unroll
        for (int j = 0; j < 8; j++)
            #pragma unroll
            for (int q = 0; q < 4; q++) acc[i][j][q] = 0.0f;

    auto issue = [&](int s) {
        uint32_t sbuf = sb + (uint32_t)(s & 1) * STAGE_BYTES;
        int kt = s * 64;
        #pragma unroll
        for (int c = 0; c < 8; ++c)
            CP_ASYNC16(sbuf + soA + (uint32_t)(16 * c) * 144,
                       A + gA + (size_t)(16 * c) * LD + kt);
        #pragma unroll
        for (int c = 0; c < 8; ++c)
            CP_ASYNC16(sbuf + MAT_BYTES + soA + (uint32_t)(16 * c) * 144,
                       B + gB + (size_t)(16 * c) * LD + kt);
    };

    issue(0); CP_COMMIT();

    uint32_t a_off = (uint32_t)(wm * 64 + (lane & 15)) * 144 + (uint32_t)((lane >> 4) * 8) * 2;
    uint32_t b_off = (uint32_t)(wn * 64 + (lane & 7) + ((lane >> 4) << 3)) * 144
                   + (uint32_t)(((lane >> 3) & 1) * 8) * 2;

    #pragma unroll 1
    for (int s = 0; s < NS; ++s) {
        CP_WAIT0();
        __syncthreads();

        uint32_t buf = sb + (uint32_t)(s & 1) * STAGE_BYTES;

        // splice: ks=0 A fragments before issuing next stage loads
        uint32_t ah[4][4];
        #pragma unroll
        for (int i = 0; i < 4; ++i)
            LDMATRIX_X4(ah[i][0], ah[i][1], ah[i][2], ah[i][3],
                        buf + a_off + (uint32_t)(i * 16) * 144);

        if (s + 1 < NS) issue(s + 1);
        CP_COMMIT();

        #pragma unroll
        for (int ks = 0; ks < 4; ++ks) {
            uint32_t kb = (uint32_t)ks * 32;
            if (ks > 0) {
                #pragma unroll
                for (int i = 0; i < 4; ++i)
                    LDMATRIX_X4(ah[i][0], ah[i][1], ah[i][2], ah[i][3],
                                buf + a_off + (uint32_t)(i * 16) * 144 + kb);
            }
            #pragma unroll
            for (int h = 0; h < 2; ++h) {
                uint32_t bh[4][2];
                #pragma unroll
                for (int jj = 0; jj < 2; ++jj)
                    LDMATRIX_X4(bh[2*jj][0], bh[2*jj][1], bh[2*jj+1][0], bh[2*jj+1][1],
                                buf + MAT_BYTES + b_off
                                + (uint32_t)(h * 32 + jj * 16) * 144 + kb);
                #pragma unroll
                for (int i = 0; i < 4; ++i)
                    #pragma unroll
                    for (int j = 0; j < 4; ++j)
                        MMA_FP16(acc[i][h * 4 + j], ah[i], bh[j][0], bh[j][1]);
            }
        }
    }
    __syncthreads();   // reads done before next job's loads overwrite smem

    int g = lane >> 2, tq = lane & 3;
    #pragma unroll
    for (int i = 0; i < 4; ++i) {
        int row0 = mBase + wm * 64 + i * 16 + g;
        int row1 = row0 + 8;
        #pragma unroll
        for (int j = 0; j < 8; ++j) {
            int nloc = wn * 64 + j * 8 + tq * 2;
            float b0 = bias_s[nloc], b1 = bias_s[nloc + 1];
            float v0 = acc[i][j][0] + b0, v1 = acc[i][j][1] + b1;
            float v2 = acc[i][j][2] + b0, v3 = acc[i][j][3] + b1;
            if (IS_GEMM1) {
                v0 = gelu_exact(v0); v1 = gelu_exact(v1);
                v2 = gelu_exact(v2); v3 = gelu_exact(v3);
                size_t o0 = (size_t)row0 * K2 + nBase + nloc;
                size_t o1 = (size_t)row1 * K2 + nBase + nloc;
                *(__half2*)(OutH + o0) = __floats2half2_rn(v0, v1);
                *(__half2*)(OutH + o1) = __floats2half2_rn(v2, v3);
            } else {
                size_t o0 = (size_t)row0 * D_IN + nBase + nloc;
                size_t o1 = (size_t)row1 * D_IN + nBase + nloc;
                *(float2*)(OutF + o0) = make_float2(v0, v1);
                *(float2*)(OutF + o1) = make_float2(v2, v3);
            }
        }
    }
}

// --- persistent scheduler, lora interleaved into GEMM1 groups ---
// tickets:
//   [0, 816):        48 blocks of 17: r<16 -> g1(m=b, n=r); r==16 -> lora(m=b)
//   [816, 8040):    344 blocks of 21: r<16 -> g1(m=48+b, n=r);
//                    r==16 -> lora(m=48+b); r>16 -> g2(m=b, n=r-17)
//   [8040, 8232):   trailing g2 rows 344..391 (4 tiles each)
// g2 deps (16 g1 + 1 lora of row m, counter target 17) are >=48 blocks
// (~1000 tickets) earlier -> never blocks with 444 CTAs in flight.
__global__ __launch_bounds__(128, 3) void mega_kernel(
    const float* __restrict__ b1, const float* __restrict__ b2,
    const float* __restrict__ probs, const int* __restrict__ idx,
    float* __restrict__ out)
{
    extern __shared__ char sm[];
    __shared__ int s_job;
    int tid = threadIdx.x;

    for (;;) {
        __syncthreads();
        if (tid == 0) s_job = atomicAdd(&g_ticket, 1);
        __syncthreads();
        int job = s_job;
        if (job >= NJOBS) return;

        int type, m, n = 0;
        if (job < 816) {
            int b = job / 17, r = job % 17;
            if (r < 16) { type = 1; m = b; n = r; }
            else        { type = 0; m = b; }
        } else if (job < 8040) {
            int j = job - 816;
            int b = j / 21, r = j % 21;
            if (r < 16)      { type = 1; m = 48 + b; n = r; }
            else if (r == 16){ type = 0; m = 48 + b; }
            else             { type = 2; m = b; n = r - 17; }
        } else {
            int t = job - 8040;
            type = 2; m = 344 + (t >> 2); n = t & 3;
        }

        if (type == 0) {
            do_lora(m, probs, idx, sm, tid);
            __threadfence();
            __syncthreads();
            if (tid == 0) atomicAdd(&g_rowdone[m], 1);
        } else if (type == 1) {
            do_gemm<D_IN, D_IN, true>(m * 128, n * 128, g_xh, g_w1t, b1,
                                      g_h, nullptr, sm, tid);
            __threadfence();
            __syncthreads();
            if (tid == 0) atomicAdd(&g_rowdone[m], 1);
        } else {
            if (tid == 0) {
                while (atomicAdd(&g_rowdone[m], 0) < 17) __nanosleep(128);
            }
            __syncthreads();
            __threadfence();
            do_gemm<K2, K2, false>(m * 128, n * 128, g_h, g_w2e, b2,
                                   nullptr, out, sm, tid);
        }
    }
}

// =====================================================================
// launch
// =====================================================================
extern "C" void kernel_launch(void* const* d_in, const int* in_sizes, int n_in,
                              void* d_out, int out_size) {
    const float* x          = (const float*)d_in[0];
    const float* W1         = (const float*)d_in[1];
    const float* b1         = (const float*)d_in[2];
    const float* W2         = (const float*)d_in[3];
    const float* b2         = (const float*)d_in[4];
    const float* w_down     = (const float*)d_in[5];
    const float* w_up       = (const float*)d_in[6];
    const float* topk_probs = (const float*)d_in[8];
    const int*   topk_idx   = (const int*)d_in[9];
    float* out = (float*)d_out;
    (void)in_sizes; (void)n_in; (void)out_size;

    cudaFuncSetAttribute(mega_kernel,
                         cudaFuncAttributeMaxDynamicSharedMemorySize, GSMEM_BYTES);

    prep_all_kernel<<<PREP_BLKS, 256>>>(x, W1, W2, w_up, w_down);
    mega_kernel<<<444, 128, GSMEM_BYTES>>>(b1, b2, topk_probs, topk_idx, out);
}

// round 17
// speedup vs baseline: 1.1934x; 1.0762x over previous
#include <cuda_runtime.h>
#include <cuda_fp16.h>
#include <cstdint>

// ---------------- problem constants ----------------
#define T_TOK 50176     // 64*28*28 tokens
#define D_IN  512
#define D_HID 2048
#define K2    2112      // D_HID + 24 moe cols + 40 zero pad (multiple of 64)
#define N_EXP 3
#define R_LORA 8

#define NROW  392       // token row-blocks of 128
#define NJOBS 8232      // 392 lora + 6272 gemm1 + 1568 gemm2

// ---------------- device scratch ----------------
__device__ __half g_xh[(size_t)T_TOK * D_IN];        // x in fp16
__device__ __half g_w1t[(size_t)D_HID * D_IN];       // W1^T [2048,512]
__device__ __half g_w2e[(size_t)D_IN * K2];          // [512,2112] = W2^T ++ w_up^T ++ 0
__device__ __half g_wdt[(size_t)32 * D_IN];          // w_down^T padded [32,512]
__device__ __half g_h[(size_t)T_TOK * K2];           // hidden ++ a24 ++ 0-pad
__device__ int    g_ticket;
__device__ int    g_rowdone[NROW];

// fast GELU: tanh form with HW tanh.approx (max ~8e-4 abs dev from exact erf)
__device__ __forceinline__ float gelu_fast(float v) {
    float u = 0.7978845608028654f * fmaf(0.044715f * v * v, v, v);
    float t;
    asm("tanh.approx.f32 %0, %1;" : "=f"(t) : "f"(u));
    return 0.5f * v * (1.0f + t);
}
__device__ __forceinline__ uint32_t smem_to_u32(const void* p) {
    uint32_t a;
    asm("{ .reg .u64 t; cvta.to.shared.u64 t, %1; cvt.u32.u64 %0, t; }" : "=r"(a) : "l"(p));
    return a;
}

// ---------------- base-ISA async copy / ldmatrix / mma helpers ----------
#define CP_ASYNC16(dst_smem, src_gmem) \
    asm volatile("cp.async.cg.shared.global [%0], [%1], 16;" \
        :: "r"(dst_smem), "l"(src_gmem) : "memory")
#define CP_COMMIT() asm volatile("cp.async.commit_group;" ::: "memory")
#define CP_WAIT1()  asm volatile("cp.async.wait_group 1;" ::: "memory")
#define CP_WAIT0()  asm volatile("cp.async.wait_group 0;" ::: "memory")

#define LDMATRIX_X4(r0, r1, r2, r3, addr) \
    asm volatile("ldmatrix.sync.aligned.m8n8.x4.shared.b16 {%0,%1,%2,%3}, [%4];" \
        : "=r"(r0), "=r"(r1), "=r"(r2), "=r"(r3) : "r"(addr))

#define MMA_FP16(c, a, b0_, b1_) \
    asm volatile("mma.sync.aligned.m16n8k16.row.col.f32.f16.f16.f32 " \
        "{%0,%1,%2,%3}, {%4,%5,%6,%7}, {%8,%9}, {%0,%1,%2,%3};" \
        : "+f"((c)[0]), "+f"((c)[1]), "+f"((c)[2]), "+f"((c)[3]) \
        : "r"((a)[0]), "r"((a)[1]), "r"((a)[2]), "r"((a)[3]), "r"(b0_), "r"(b1_))

// =====================================================================
// Fused prep: reset + x cvt + all weight prep in ONE launch.
// =====================================================================
#define CVT_BLKS   25088   // 50176*512/4/256
#define PREP_BLKS  (CVT_BLKS + 1024 + 1024 + 192 + 1)

__global__ __launch_bounds__(256) void prep_all_kernel(
    const float* __restrict__ x,
    const float* __restrict__ W1, const float* __restrict__ W2,
    const float* __restrict__ w_up, const float* __restrict__ w_down)
{
    __shared__ float tile[32][33];
    int b = blockIdx.x;
    if (b < CVT_BLKS) {
        int i = b * 256 + threadIdx.x;
        float4 v = ((const float4*)x)[i];
        ((__half2*)g_xh)[2*i]   = __floats2half2_rn(v.x, v.y);
        ((__half2*)g_xh)[2*i+1] = __floats2half2_rn(v.z, v.w);
        return;
    }
    b -= CVT_BLKS;
    int tx = threadIdx.x & 31, ty = threadIdx.x >> 5;
    if (b < 1024) {
        int c0 = (b & 63) * 32, r0 = (b >> 6) * 32;   // cols of W1 (2048), rows (512)
        #pragma unroll
        for (int i = 0; i < 4; i++)
            tile[ty + 8*i][tx] = W1[(size_t)(r0 + ty + 8*i) * D_HID + c0 + tx];
        __syncthreads();
        #pragma unroll
        for (int i = 0; i < 4; i++)
            g_w1t[(size_t)(c0 + ty + 8*i) * D_IN + r0 + tx] = __float2half_rn(tile[tx][ty + 8*i]);
    } else if (b < 2048) {
        int b2 = b - 1024;
        int c0 = (b2 & 15) * 32, r0 = (b2 >> 4) * 32; // cols of W2 (512), rows (2048)
        #pragma unroll
        for (int i = 0; i < 4; i++)
            tile[ty + 8*i][tx] = W2[(size_t)(r0 + ty + 8*i) * D_IN + c0 + tx];
        __syncthreads();
        #pragma unroll
        for (int i = 0; i < 4; i++)
            g_w2e[(size_t)(c0 + ty + 8*i) * K2 + r0 + tx] = __float2half_rn(tile[tx][ty + 8*i]);
    } else if (b < 2240) {
        int b3 = b - 2048;
        if (b3 < 128) {
            int i = b3 * 256 + threadIdx.x;          // over 512*64
            int n = i >> 6, c = i & 63;
            float v = 0.0f;
            if (c < N_EXP * R_LORA) v = w_up[(size_t)c * D_IN + n];
            g_w2e[(size_t)n * K2 + D_HID + c] = __float2half_rn(v);
        } else {
            int i = (b3 - 128) * 256 + threadIdx.x;  // over 32*512
            int n = i >> 9, d = i & 511;
            float v = 0.0f;
            if (n < N_EXP * R_LORA) {
                int e = n >> 3, r = n & 7;
                v = w_down[(size_t)e * (D_IN * R_LORA) + (size_t)d * R_LORA + r];
            }
            g_wdt[(size_t)n * D_IN + d] = __float2half_rn(v);
        }
    } else {
        int i = threadIdx.x;
        if (i == 0) g_ticket = 0;
        for (int j = i; j < NROW; j += 256) g_rowdone[j] = 0;
    }
}

// =====================================================================
// Mega-kernel pieces (128-thread CTAs, 3 CTA/SM)
// GEMM stage = k64: per matrix 128 rows x 72 halfs (144 B pitch).
// =====================================================================
#define MAT_BYTES 18432     // 128 * 72 * 2
#define STAGE_BYTES 36864   // A + B
#define GSMEM_BYTES (2 * STAGE_BYTES + 512)

#define LMAT_A 10240        // lora keeps k32 / pitch-80 layout
#define LSTAGE 12800

// --- LoRA job: down = x @ wdt^T [128 tok x 32], gated-gelu epilogue ---
__device__ void do_lora(int m, const float* __restrict__ probs,
                        const int* __restrict__ idx, char* sm, int tid)
{
    uint32_t sb = smem_to_u32(sm);
    int lane = tid & 31, w = tid >> 5;
    int mBase = m * 128;
    const int NS = D_IN / 32;   // 16

    float acc[2][4][4];
    #pragma unroll
    for (int i = 0; i < 2; i++)
        #pragma unroll
        for (int j = 0; j < 4; j++)
            #pragma unroll
            for (int q = 0; q < 4; q++) acc[i][j][q] = 0.0f;

    auto issue = [&](int s) {
        uint32_t sbuf = sb + (uint32_t)(s % 3) * LSTAGE;
        int kt = s * 32;
        #pragma unroll
        for (int c = 0; c < 4; ++c) {
            int q = tid + 128 * c;
            int row = q >> 2, ch = q & 3;
            CP_ASYNC16(sbuf + (uint32_t)row * 80 + (uint32_t)ch * 16,
                       g_xh + (size_t)(mBase + row) * D_IN + kt + ch * 8);
        }
        {
            int row = tid >> 2, ch = tid & 3;
            CP_ASYNC16(sbuf + LMAT_A + (uint32_t)row * 80 + (uint32_t)ch * 16,
                       g_wdt + (size_t)row * D_IN + kt + ch * 8);
        }
    };

    issue(0); CP_COMMIT();
    issue(1); CP_COMMIT();

    uint32_t a_off = (uint32_t)(w * 32 + (lane & 15)) * 80 + (uint32_t)((lane >> 4) * 8) * 2;
    uint32_t b_off = LMAT_A + (uint32_t)((lane & 7) + ((lane >> 4) << 3)) * 80
                   + (uint32_t)(((lane >> 3) & 1) * 8) * 2;

    #pragma unroll 1
    for (int s = 0; s < NS; ++s) {
        CP_WAIT1();
        __syncthreads();
        if (s + 2 < NS) issue(s + 2);
        CP_COMMIT();

        uint32_t buf = sb + (uint32_t)(s % 3) * LSTAGE;
        #pragma unroll
        for (int ks = 0; ks < 2; ++ks) {
            uint32_t kb = (uint32_t)ks * 32;
            uint32_t ah[2][4], bh[4][2];
            #pragma unroll
            for (int i = 0; i < 2; ++i)
                LDMATRIX_X4(ah[i][0], ah[i][1], ah[i][2], ah[i][3],
                            buf + a_off + (uint32_t)(i * 16) * 80 + kb);
            #pragma unroll
            for (int jj = 0; jj < 2; ++jj)
                LDMATRIX_X4(bh[2*jj][0], bh[2*jj][1], bh[2*jj+1][0], bh[2*jj+1][1],
                            buf + b_off + (uint32_t)(jj * 16) * 80 + kb);
            #pragma unroll
            for (int i = 0; i < 2; ++i)
                #pragma unroll
                for (int j = 0; j < 4; ++j)
                    MMA_FP16(acc[i][j], ah[i], bh[j][0], bh[j][1]);
        }
    }
    __syncthreads();   // reads done before smem reuse by next job

    int g = lane >> 2, tq = lane & 3;
    #pragma unroll
    for (int i = 0; i < 2; ++i) {
        int t0 = mBase + w * 32 + i * 16 + g;
        int t1 = t0 + 8;
        int e00 = idx[2*t0], e01 = idx[2*t0+1];
        int e10 = idx[2*t1], e11 = idx[2*t1+1];
        float p00 = probs[2*t0], p01 = probs[2*t0+1];
        float p10 = probs[2*t1], p11 = probs[2*t1+1];
        #pragma unroll
        for (int j = 0; j < 3; ++j) {          // j == expert id
            float w0 = (e00 == j) ? p00 : ((e01 == j) ? p01 : 0.0f);
            float w1 = (e10 == j) ? p10 : ((e11 == j) ? p11 : 0.0f);
            float v0 = w0 * gelu_fast(acc[i][j][0]);
            float v1 = w0 * gelu_fast(acc[i][j][1]);
            float v2 = w1 * gelu_fast(acc[i][j][2]);
            float v3 = w1 * gelu_fast(acc[i][j][3]);
            int c = j * 8 + tq * 2;
            *(__half2*)(g_h + (size_t)t0 * K2 + D_HID + c) = __floats2half2_rn(v0, v1);
            *(__half2*)(g_h + (size_t)t1 * K2 + D_HID + c) = __floats2half2_rn(v2, v3);
        }
    }
}

// --- GEMM job: CTA 128x128, 4 warps (64x64), k64 stages, 2-buffer
//     cp.async pipeline with A-fragment splice. (round-13 proven body) ---
template<int KTOT, int LD, bool IS_GEMM1>
__device__ void do_gemm(int mBase, int nBase,
                        const __half* __restrict__ A, const __half* __restrict__ B,
                        const float* __restrict__ bias,
                        __half* __restrict__ OutH, float* __restrict__ OutF,
                        char* sm, int tid)
{
    uint32_t sb = smem_to_u32(sm);
    float* bias_s = (float*)(sm + 2 * STAGE_BYTES);

    int lane = tid & 31, wid = tid >> 5;
    int wm = wid >> 1, wn = wid & 1;          // warp grid 2 x 2

    int r0 = tid >> 3, ch = tid & 7;
    size_t gA = (size_t)(mBase + r0) * LD + ch * 8;
    size_t gB = (size_t)(nBase + r0) * LD + ch * 8;
    uint32_t soA = (uint32_t)r0 * 144 + (uint32_t)ch * 16;

    const int NS = KTOT / 64;

    float acc[4][8][4];
    #pragma unroll
    for (int i = 0; i < 4; i++)
        #pragma unroll
        for (int j = 0; j < 8; j++)
            #pragma unroll
            for (int q = 0; q < 4; q++) acc[i][j][q] = 0.0f;

    auto issue = [&](int s) {
        uint32_t sbuf = sb + (uint32_t)(s & 1) * STAGE_BYTES;
        int kt = s * 64;
        #pragma unroll
        for (int c = 0; c < 8; ++c)
            CP_ASYNC16(sbuf + soA + (uint32_t)(16 * c) * 144,
                       A + gA + (size_t)(16 * c) * LD + kt);
        #pragma unroll
        for (int c = 0; c < 8; ++c)
            CP_ASYNC16(sbuf + MAT_BYTES + soA + (uint32_t)(16 * c) * 144,
                       B + gB + (size_t)(16 * c) * LD + kt);
    };

    issue(0); CP_COMMIT();
    bias_s[tid] = bias[nBase + tid];   // after stage-0 issue

    uint32_t a_off = (uint32_t)(wm * 64 + (lane & 15)) * 144 + (uint32_t)((lane >> 4) * 8) * 2;
    uint32_t b_off = (uint32_t)(wn * 64 + (lane & 7) + ((lane >> 4) << 3)) * 144
                   + (uint32_t)(((lane >> 3) & 1) * 8) * 2;

    #pragma unroll 1
    for (int s = 0; s < NS; ++s) {
        CP_WAIT0();
        __syncthreads();

        uint32_t buf = sb + (uint32_t)(s & 1) * STAGE_BYTES;

        // splice: ks=0 A fragments before issuing next stage loads
        uint32_t ah[4][4];
        #pragma unroll
        for (int i = 0; i < 4; ++i)
            LDMATRIX_X4(ah[i][0], ah[i][1], ah[i][2], ah[i][3],
                        buf + a_off + (uint32_t)(i * 16) * 144);

        if (s + 1 < NS) issue(s + 1);
        CP_COMMIT();

        #pragma unroll
        for (int ks = 0; ks < 4; ++ks) {
            uint32_t kb = (uint32_t)ks * 32;
            if (ks > 0) {
                #pragma unroll
                for (int i = 0; i < 4; ++i)
                    LDMATRIX_X4(ah[i][0], ah[i][1], ah[i][2], ah[i][3],
                                buf + a_off + (uint32_t)(i * 16) * 144 + kb);
            }
            #pragma unroll
            for (int h = 0; h < 2; ++h) {
                uint32_t bh[4][2];
                #pragma unroll
                for (int jj = 0; jj < 2; ++jj)
                    LDMATRIX_X4(bh[2*jj][0], bh[2*jj][1], bh[2*jj+1][0], bh[2*jj+1][1],
                                buf + MAT_BYTES + b_off
                                + (uint32_t)(h * 32 + jj * 16) * 144 + kb);
                #pragma unroll
                for (int i = 0; i < 4; ++i)
                    #pragma unroll
                    for (int j = 0; j < 4; ++j)
                        MMA_FP16(acc[i][h * 4 + j], ah[i], bh[j][0], bh[j][1]);
            }
        }
    }
    __syncthreads();   // reads done before next job's loads overwrite smem

    int g = lane >> 2, tq = lane & 3;
    #pragma unroll
    for (int i = 0; i < 4; ++i) {
        int row0 = mBase + wm * 64 + i * 16 + g;
        int row1 = row0 + 8;
        #pragma unroll
        for (int j = 0; j < 8; ++j) {
            int nloc = wn * 64 + j * 8 + tq * 2;
            float b0 = bias_s[nloc], b1 = bias_s[nloc + 1];
            float v0 = acc[i][j][0] + b0, v1 = acc[i][j][1] + b1;
            float v2 = acc[i][j][2] + b0, v3 = acc[i][j][3] + b1;
            if (IS_GEMM1) {
                v0 = gelu_fast(v0); v1 = gelu_fast(v1);
                v2 = gelu_fast(v2); v3 = gelu_fast(v3);
                size_t o0 = (size_t)row0 * K2 + nBase + nloc;
                size_t o1 = (size_t)row1 * K2 + nBase + nloc;
                *(__half2*)(OutH + o0) = __floats2half2_rn(v0, v1);
                *(__half2*)(OutH + o1) = __floats2half2_rn(v2, v3);
            } else {
                size_t o0 = (size_t)row0 * D_IN + nBase + nloc;
                size_t o1 = (size_t)row1 * D_IN + nBase + nloc;
                *(float2*)(OutF + o0) = make_float2(v0, v1);
                *(float2*)(OutF + o1) = make_float2(v2, v3);
            }
        }
    }
}

// --- persistent scheduler (round-13 job map) ---
__global__ __launch_bounds__(128, 3) void mega_kernel(
    const float* __restrict__ b1, const float* __restrict__ b2,
    const float* __restrict__ probs, const int* __restrict__ idx,
    float* __restrict__ out)
{
    extern __shared__ char sm[];
    __shared__ int s_job;
    int tid = threadIdx.x;

    for (;;) {
        __syncthreads();
        if (tid == 0) s_job = atomicAdd(&g_ticket, 1);
        __syncthreads();
        int job = s_job;
        if (job >= NJOBS) return;

        int type, m, n = 0;
        if (job < 392) { type = 0; m = job; }
        else {
            int j = job - 392;
            if (j < 768) { type = 1; m = j >> 4; n = j & 15; }
            else if (j < 7648) {
                int t = j - 768, b = t / 20, r = t % 20;
                if (r < 16) { type = 1; m = 48 + b; n = r; }
                else        { type = 2; m = b;      n = r - 16; }
            } else {
                int t = j - 7648; type = 2; m = 344 + (t >> 2); n = t & 3;
            }
        }

        if (type == 0) {
            do_lora(m, probs, idx, sm, tid);
            __threadfence();
            __syncthreads();
            if (tid == 0) atomicAdd(&g_rowdone[m], 1);
        } else if (type == 1) {
            do_gemm<D_IN, D_IN, true>(m * 128, n * 128, g_xh, g_w1t, b1,
                                      g_h, nullptr, sm, tid);
            __threadfence();
            __syncthreads();
            if (tid == 0) atomicAdd(&g_rowdone[m], 1);
        } else {
            if (tid == 0) {
                while (atomicAdd(&g_rowdone[m], 0) < 17) __nanosleep(128);
            }
            __syncthreads();
            __threadfence();
            do_gemm<K2, K2, false>(m * 128, n * 128, g_h, g_w2e, b2,
                                   nullptr, out, sm, tid);
        }
    }
}

// =====================================================================
// launch
// =====================================================================
extern "C" void kernel_launch(void* const* d_in, const int* in_sizes, int n_in,
                              void* d_out, int out_size) {
    const float* x          = (const float*)d_in[0];
    const float* W1         = (const float*)d_in[1];
    const float* b1         = (const float*)d_in[2];
    const float* W2         = (const float*)d_in[3];
    const float* b2         = (const float*)d_in[4];
    const float* w_down     = (const float*)d_in[5];
    const float* w_up       = (const float*)d_in[6];
    const float* topk_probs = (const float*)d_in[8];
    const int*   topk_idx   = (const int*)d_in[9];
    float* out = (float*)d_out;
    (void)in_sizes; (void)n_in; (void)out_size;

    cudaFuncSetAttribute(mega_kernel,
                         cudaFuncAttributeMaxDynamicSharedMemorySize, GSMEM_BYTES);

    prep_all_kernel<<<PREP_BLKS, 256>>>(x, W1, W2, w_up, w_down);
    mega_kernel<<<444, 128, GSMEM_BYTES>>>(b1, b2, topk_probs, topk_idx, out);
}